// round 5
// baseline (speedup 1.0000x reference)
#include <cuda_runtime.h>
#include <cstdint>

// ColorHistogramLoss — soft 64-bin histogram CDF L1 loss.
// R5: fully fused single kernel. 384 blocks bin pixel slices into shared,
// flush moments to global; the last block per image (ticket) gathers that
// image's soft histogram + cdf; the last image-winner (global ticket)
// reduces the 768-term |cdf_p - cdf_t| mean. One launch total.

namespace chl {

constexpr int BINS    = 64;
constexpr int TSUB    = 32;              // subcells per bin
constexpr int NSUB    = BINS * TSUB;     // 2048 subcells over [0,1)
constexpr int NCH     = 12;              // B*C
constexpr int NIMG    = 24;              // 2 tensors * 12 channels
constexpr int PIX     = 65536;           // H*W
constexpr int SLICES  = 16;
constexpr int PIX_BLK = PIX / SLICES;    // 4096
constexpr int THR     = 256;
constexpr int NTAP    = 10;              // 320 taps ~ |d| <= 5 bins
constexpr int PAD     = 160;
constexpr int CSZ     = NSUB + 2 * PAD;  // 2368

__device__ unsigned long long g_acc[NIMG * NSUB];  // packed (cnt<<40)|sum(f*2^20); zero-init
__device__ float g_cdf[NIMG * BINS];
__device__ int   g_cnt_img[NIMG];                  // zero-init; winners reset
__device__ int   g_count;                          // zero-init; winner resets

__global__ void __launch_bounds__(THR) k_all(const float* __restrict__ pred,
                                             const float* __restrict__ tgt,
                                             float* __restrict__ out) {
  __shared__ unsigned long long sh[NSUB];          // 16KB binning accumulator
  __shared__ float cnt_sh[CSZ], sd_sh[CSZ];        // 18.5KB moments (winner only)
  __shared__ float hist_sh[BINS];
  __shared__ float red_sh[8];
  __shared__ int tick_sh;

  int tid   = threadIdx.x;
  int warp  = tid >> 5, lane = tid & 31;
  int blk   = blockIdx.x;
  int img   = blk / SLICES;             // 0..23
  int slice = blk % SLICES;
  const float* src = (img < NCH ? pred : tgt) + (img % NCH) * PIX + slice * PIX_BLK;

  // ---------- phase 1: bin this slice ----------
  for (int i = tid; i < NSUB; i += THR) sh[i] = 0ULL;
  __syncthreads();

  const float4* p4 = reinterpret_cast<const float4*>(src);
#pragma unroll
  for (int it = 0; it < PIX_BLK / 4 / THR; ++it) {
    float4 v = p4[it * THR + tid];
    float xs[4] = {v.x, v.y, v.z, v.w};
#pragma unroll
    for (int k = 0; k < 4; ++k) {
      float su = xs[k] * 2048.0f;          // exact: power-of-2 scale
      int s = (int)su;
      s = max(0, min(NSUB - 1, s));
      float f = su - (float)s;             // in-cell position, [0,1)
      unsigned q = (unsigned)__float2int_rn(f * 1048576.0f);  // f*2^20
      atomicAdd(&sh[s], (1ULL << 40) | (unsigned long long)q);
    }
  }
  __syncthreads();

  unsigned long long* g = g_acc + img * NSUB;
  for (int i = tid; i < NSUB; i += THR) {
    unsigned long long v = sh[i];
    if (v) atomicAdd(&g[i], v);
  }

  // ---------- per-image ticket: last slice-block does the histogram ----------
  __threadfence();
  __syncthreads();
  if (tid == 0) tick_sh = atomicAdd(&g_cnt_img[img], 1);
  __syncthreads();
  if (tick_sh != SLICES - 1) return;
  __threadfence();
  if (tid == 0) g_cnt_img[img] = 0;        // reset for next replay

  // ---------- phase 2: soft histogram + cdf for this image ----------
  if (tid < PAD) {
    cnt_sh[tid] = 0.0f;  sd_sh[tid] = 0.0f;
    cnt_sh[CSZ - 1 - tid] = 0.0f;  sd_sh[CSZ - 1 - tid] = 0.0f;
  }
  for (int i = tid; i < NSUB; i += THR) {
    unsigned long long v = g[i];
    g[i] = 0ULL;                                   // re-zero for next replay
    float cnt = (float)(unsigned)(v >> 40);
    float lo  = (float)(v & ((1ULL << 40) - 1ULL));
    cnt_sh[i + PAD] = cnt;
    sd_sh[i + PAD]  = lo * 0x1p-20f - cnt * 0.5f;  // sum of (f - 0.5)
  }

  // register-resident Gaussian taps: o = lane + 32t, d = (o - 159.5)/32
  float w[NTAP], wp[NTAP];
#pragma unroll
  for (int t = 0; t < NTAP; ++t) {
    float d = ((float)(lane + 32 * t) - 159.5f) * (1.0f / 32.0f);
    float e = __expf(-0.5f * d * d);
    w[t]  = e;
    wp[t] = -d * e * (1.0f / 32.0f);
  }
  __syncthreads();

  // each warp gathers 8 bins, conflict-free. padded base = 32j + 16 + lane
  // (sbase = 32j - 144 so d = (s+0.5)/32 - (j+0.5) matches the tap grid).
#pragma unroll
  for (int jj = 0; jj < 8; ++jj) {
    int j = warp * 8 + jj;
    int base = TSUB * j + 16 + lane;
    float a0 = 0.0f, a1 = 0.0f;
#pragma unroll
    for (int t = 0; t < NTAP; ++t) {
      a0 = fmaf(cnt_sh[base + 32 * t], w[t], a0);
      a1 = fmaf(sd_sh[base + 32 * t], wp[t], a1);
    }
    float acc = a0 + a1;
#pragma unroll
    for (int d = 16; d; d >>= 1) acc += __shfl_down_sync(0xffffffffu, acc, d);
    if (lane == 0) hist_sh[j] = acc;
  }
  __syncthreads();

  if (warp == 0) {   // 64-bin inclusive scan, normalize, write cdf
    float p0 = hist_sh[lane];
    float p1 = hist_sh[lane + 32];
#pragma unroll
    for (int d = 1; d < 32; d <<= 1) {
      float t0 = __shfl_up_sync(0xffffffffu, p0, d);
      float t1 = __shfl_up_sync(0xffffffffu, p1, d);
      if (lane >= d) { p0 += t0; p1 += t1; }
    }
    float half0 = __shfl_sync(0xffffffffu, p0, 31);
    float inv   = __frcp_rn(half0 + __shfl_sync(0xffffffffu, p1, 31) + 1e-8f);
    g_cdf[img * BINS + lane]      = p0 * inv;
    g_cdf[img * BINS + lane + 32] = (half0 + p1) * inv;
  }

  // ---------- global ticket: last image-winner reduces the loss ----------
  __threadfence();
  __syncthreads();
  if (tid == 0) tick_sh = atomicAdd(&g_count, 1);
  __syncthreads();
  if (tick_sh != NIMG - 1) return;
  __threadfence();
  if (tid == 0) g_count = 0;               // reset for next replay

  float s = 0.0f;
  for (int i = tid; i < NCH * BINS; i += THR)
    s += fabsf(g_cdf[i] - g_cdf[i + NCH * BINS]);
#pragma unroll
  for (int d = 16; d; d >>= 1) s += __shfl_down_sync(0xffffffffu, s, d);
  if (lane == 0) red_sh[warp] = s;
  __syncthreads();
  if (tid == 0) {
    float tot = 0.0f;
#pragma unroll
    for (int wv = 0; wv < 8; ++wv) tot += red_sh[wv];
    out[0] = tot / (float)(NCH * BINS);
  }
}

}  // namespace chl

extern "C" void kernel_launch(void* const* d_in, const int* in_sizes, int n_in,
                              void* d_out, int out_size) {
  const float* pred = (const float*)d_in[0];
  const float* tgt  = (const float*)d_in[1];
  float* out = (float*)d_out;

  chl::k_all<<<chl::NIMG * chl::SLICES, chl::THR>>>(pred, tgt, out);
}

// round 6
// speedup vs baseline: 1.2262x; 1.2262x over previous
#include <cuda_runtime.h>
#include <cstdint>

// ColorHistogramLoss — soft 64-bin histogram CDF L1 loss.
// R6: one kernel, no per-image winner phase. Each of 384 blocks bins its
// 4096-pixel slice into shared moments, gathers the 64-bin soft histogram
// LOCALLY from its own smem, and flushes 64 fixed-point values via integer
// atomicAdd (deterministic). The 384th block (ticket) scans cdfs and
// reduces the loss.

namespace chl {

constexpr int BINS    = 64;
constexpr int TSUB    = 32;              // subcells per bin
constexpr int NSUB    = BINS * TSUB;     // 2048 subcells over [0,1)
constexpr int NCH     = 12;              // B*C
constexpr int NIMG    = 24;              // 2 tensors * 12 channels
constexpr int PIX     = 65536;           // H*W
constexpr int SLICES  = 16;
constexpr int PIX_BLK = PIX / SLICES;    // 4096
constexpr int NBLK    = NIMG * SLICES;   // 384
constexpr int THR     = 256;
constexpr int NTAP    = 10;              // 320 taps ~ |d| <= 5 bins
constexpr int PAD     = 160;
constexpr int CSZ     = NSUB + 2 * PAD;  // 2368
constexpr float QS    = 262144.0f;       // 2^18 fixed-point scale

__device__ unsigned long long g_histq[NIMG * BINS]; // zero-init; final block re-zeros
__device__ int g_count;                             // zero-init; final block resets

__global__ void __launch_bounds__(THR) k_all(const float* __restrict__ pred,
                                             const float* __restrict__ tgt,
                                             float* __restrict__ out) {
  __shared__ unsigned long long sh[NSUB];          // 16KB binning accumulator
  __shared__ float cnt_sh[CSZ], sd_sh[CSZ];        // 18.5KB padded moments
  __shared__ float cdf_sh[NIMG][BINS];             // final phase only
  __shared__ float red_sh[8];
  __shared__ int tick_sh;

  int tid   = threadIdx.x;
  int warp  = tid >> 5, lane = tid & 31;
  int blk   = blockIdx.x;
  int img   = blk / SLICES;             // 0..23
  int slice = blk % SLICES;
  const float* src = (img < NCH ? pred : tgt) + (img % NCH) * PIX + slice * PIX_BLK;

  // ---------- phase 1: bin this slice into shared moments ----------
  for (int i = tid; i < NSUB; i += THR) sh[i] = 0ULL;
  // register-resident Gaussian taps: o = lane + 32t, d = (o - 159.5)/32
  float w[NTAP], wp[NTAP];
#pragma unroll
  for (int t = 0; t < NTAP; ++t) {
    float d = ((float)(lane + 32 * t) - 159.5f) * (1.0f / 32.0f);
    float e = __expf(-0.5f * d * d);
    w[t]  = e;
    wp[t] = -d * e * (1.0f / 32.0f);
  }
  __syncthreads();

  const float4* p4 = reinterpret_cast<const float4*>(src);
#pragma unroll
  for (int it = 0; it < PIX_BLK / 4 / THR; ++it) {
    float4 v = p4[it * THR + tid];
    float xs[4] = {v.x, v.y, v.z, v.w};
#pragma unroll
    for (int k = 0; k < 4; ++k) {
      float su = xs[k] * 2048.0f;          // exact: power-of-2 scale
      int s = (int)su;
      s = max(0, min(NSUB - 1, s));
      float f = su - (float)s;             // in-cell position, [0,1)
      unsigned q = (unsigned)__float2int_rn(f * 1048576.0f);  // f*2^20
      atomicAdd(&sh[s], (1ULL << 40) | (unsigned long long)q);
    }
  }
  __syncthreads();

  // ---------- phase 2: unpack moments to padded float arrays ----------
  if (tid < PAD) {
    cnt_sh[tid] = 0.0f;  sd_sh[tid] = 0.0f;
    cnt_sh[CSZ - 1 - tid] = 0.0f;  sd_sh[CSZ - 1 - tid] = 0.0f;
  }
  for (int i = tid; i < NSUB; i += THR) {
    unsigned long long v = sh[i];
    float cnt = (float)(unsigned)(v >> 40);
    float lo  = (float)(v & ((1ULL << 40) - 1ULL));
    cnt_sh[i + PAD] = cnt;
    sd_sh[i + PAD]  = lo * 0x1p-20f - cnt * 0.5f;  // sum of (f - 0.5)
  }
  __syncthreads();

  // ---------- phase 3: local gather, 8 bins per warp, conflict-free ----------
  // padded base = (32j - 144) + PAD + lane = 32j + 16 + lane, so
  // d = (s+0.5)/32 - (j+0.5) matches the tap grid d=(o-159.5)/32.
#pragma unroll
  for (int jj = 0; jj < 8; ++jj) {
    int j = warp * 8 + jj;
    int base = TSUB * j + 16 + lane;
    float a0 = 0.0f, a1 = 0.0f;
#pragma unroll
    for (int t = 0; t < NTAP; ++t) {
      a0 = fmaf(cnt_sh[base + 32 * t], w[t], a0);
      a1 = fmaf(sd_sh[base + 32 * t], wp[t], a1);
    }
    float acc = a0 + a1;
#pragma unroll
    for (int d = 16; d; d >>= 1) acc += __shfl_down_sync(0xffffffffu, acc, d);
    if (lane == 0) {
      long long q = __float2ll_rn(acc * QS);       // deterministic fixed-point
      atomicAdd(&g_histq[img * BINS + j], (unsigned long long)q);
    }
  }

  // ---------- global ticket: 384th block finalizes ----------
  __threadfence();
  __syncthreads();
  if (tid == 0) tick_sh = atomicAdd(&g_count, 1);
  __syncthreads();
  if (tick_sh != NBLK - 1) return;
  __threadfence();
  if (tid == 0) g_count = 0;                       // reset for next replay

  for (int im = warp; im < NIMG; im += 8) {
    unsigned long long q0 = g_histq[im * BINS + lane];
    unsigned long long q1 = g_histq[im * BINS + 32 + lane];
    g_histq[im * BINS + lane] = 0ULL;              // re-zero for next replay
    g_histq[im * BINS + 32 + lane] = 0ULL;
    float p0 = (float)(long long)q0;
    float p1 = (float)(long long)q1;
#pragma unroll
    for (int d = 1; d < 32; d <<= 1) {
      float t0 = __shfl_up_sync(0xffffffffu, p0, d);
      float t1 = __shfl_up_sync(0xffffffffu, p1, d);
      if (lane >= d) { p0 += t0; p1 += t1; }
    }
    float half0 = __shfl_sync(0xffffffffu, p0, 31);
    float inv   = __frcp_rn(half0 + __shfl_sync(0xffffffffu, p1, 31) + 1e-8f * QS);
    cdf_sh[im][lane]      = p0 * inv;
    cdf_sh[im][lane + 32] = (half0 + p1) * inv;
  }
  __syncthreads();

  float s = 0.0f;
  for (int i = tid; i < NCH * BINS; i += THR) {
    int ch = i >> 6, jj = i & 63;
    s += fabsf(cdf_sh[ch][jj] - cdf_sh[ch + NCH][jj]);
  }
#pragma unroll
  for (int d = 16; d; d >>= 1) s += __shfl_down_sync(0xffffffffu, s, d);
  if (lane == 0) red_sh[warp] = s;
  __syncthreads();
  if (tid == 0) {
    float tot = 0.0f;
#pragma unroll
    for (int wv = 0; wv < 8; ++wv) tot += red_sh[wv];
    out[0] = tot / (float)(NCH * BINS);
  }
}

}  // namespace chl

extern "C" void kernel_launch(void* const* d_in, const int* in_sizes, int n_in,
                              void* d_out, int out_size) {
  const float* pred = (const float*)d_in[0];
  const float* tgt  = (const float*)d_in[1];
  float* out = (float*)d_out;

  chl::k_all<<<chl::NBLK, chl::THR>>>(pred, tgt, out);
}

// round 7
// speedup vs baseline: 1.6078x; 1.3113x over previous
#include <cuda_runtime.h>
#include <cstdint>

// ColorHistogramLoss — soft 64-bin histogram CDF L1 loss.
// R7: binning atomics narrowed to 32-bit: packed (cnt<<19)|sum(f*127)
// per 1/32-bin subcell. Halves shared-atomic width (the R6 bottleneck:
// L1/shared pipe 30.8%, ~26k cyc/SM of ATOMS.64). Rest of structure
// unchanged from R6 (local gather per block, fixed-point REDG flush,
// global ticket finalize).

namespace chl {

constexpr int BINS    = 64;
constexpr int TSUB    = 32;              // subcells per bin
constexpr int NSUB    = BINS * TSUB;     // 2048 subcells over [0,1)
constexpr int NCH     = 12;              // B*C
constexpr int NIMG    = 24;              // 2 tensors * 12 channels
constexpr int PIX     = 65536;           // H*W
constexpr int SLICES  = 16;
constexpr int PIX_BLK = PIX / SLICES;    // 4096
constexpr int NBLK    = NIMG * SLICES;   // 384
constexpr int THR     = 256;
constexpr int NTAP    = 10;              // 320 taps ~ |d| <= 5 bins
constexpr int PAD     = 160;
constexpr int CSZ     = NSUB + 2 * PAD;  // 2368
constexpr float QS    = 262144.0f;       // 2^18 fixed-point scale for hist flush

__device__ unsigned long long g_histq[NIMG * BINS]; // zero-init; final block re-zeros
__device__ int g_count;                             // zero-init; final block resets

__global__ void __launch_bounds__(THR) k_all(const float* __restrict__ pred,
                                             const float* __restrict__ tgt,
                                             float* __restrict__ out) {
  __shared__ unsigned sh[NSUB];                    // 8KB binning accumulator
  __shared__ float cnt_sh[CSZ], sd_sh[CSZ];        // 18.5KB padded moments
  __shared__ float cdf_sh[NIMG][BINS];             // final phase only
  __shared__ float red_sh[8];
  __shared__ int tick_sh;

  int tid   = threadIdx.x;
  int warp  = tid >> 5, lane = tid & 31;
  int blk   = blockIdx.x;
  int img   = blk / SLICES;             // 0..23
  int slice = blk % SLICES;
  const float* src = (img < NCH ? pred : tgt) + (img % NCH) * PIX + slice * PIX_BLK;

  // ---------- phase 1: bin this slice into shared 32-bit moments ----------
  for (int i = tid; i < NSUB; i += THR) sh[i] = 0u;
  __syncthreads();

  const float4* p4 = reinterpret_cast<const float4*>(src);
#pragma unroll
  for (int it = 0; it < PIX_BLK / 4 / THR; ++it) {
    float4 v = p4[it * THR + tid];
    float xs[4] = {v.x, v.y, v.z, v.w};
#pragma unroll
    for (int k = 0; k < 4; ++k) {
      float su = xs[k] * 2048.0f;          // exact: power-of-2 scale
      int s = (int)su;
      s = max(0, min(NSUB - 1, s));
      float f = su - (float)s;             // in-cell position, [0,1)
      unsigned q = (unsigned)__float2int_rn(f * 127.0f);  // 7-bit f
      atomicAdd(&sh[s], (1u << 19) | q);   // cnt [19:32), sum_q [0:19)
    }
  }
  __syncthreads();

  // ---------- phase 2: unpack moments to padded float arrays ----------
  if (tid < PAD) {
    cnt_sh[tid] = 0.0f;  sd_sh[tid] = 0.0f;
    cnt_sh[CSZ - 1 - tid] = 0.0f;  sd_sh[CSZ - 1 - tid] = 0.0f;
  }
  for (int i = tid; i < NSUB; i += THR) {
    unsigned v = sh[i];
    float cnt = (float)(v >> 19);
    float sq  = (float)(v & 0x7FFFFu);
    cnt_sh[i + PAD] = cnt;
    sd_sh[i + PAD]  = fmaf(sq, 1.0f / 127.0f, cnt * -0.5f);  // sum of (f - 0.5)
  }

  // register-resident Gaussian taps: o = lane + 32t, d = (o - 159.5)/32
  float w[NTAP], wp[NTAP];
#pragma unroll
  for (int t = 0; t < NTAP; ++t) {
    float d = ((float)(lane + 32 * t) - 159.5f) * (1.0f / 32.0f);
    float e = __expf(-0.5f * d * d);
    w[t]  = e;
    wp[t] = -d * e * (1.0f / 32.0f);
  }
  __syncthreads();

  // ---------- phase 3: local gather, 8 bins per warp, conflict-free ----------
  // padded base = (32j - 144) + PAD + lane = 32j + 16 + lane, so
  // d = (s+0.5)/32 - (j+0.5) matches the tap grid d=(o-159.5)/32.
#pragma unroll
  for (int jj = 0; jj < 8; ++jj) {
    int j = warp * 8 + jj;
    int base = TSUB * j + 16 + lane;
    float a0 = 0.0f, a1 = 0.0f;
#pragma unroll
    for (int t = 0; t < NTAP; ++t) {
      a0 = fmaf(cnt_sh[base + 32 * t], w[t], a0);
      a1 = fmaf(sd_sh[base + 32 * t], wp[t], a1);
    }
    float acc = a0 + a1;
#pragma unroll
    for (int d = 16; d; d >>= 1) acc += __shfl_down_sync(0xffffffffu, acc, d);
    if (lane == 0) {
      long long q = __float2ll_rn(acc * QS);       // deterministic fixed-point
      atomicAdd(&g_histq[img * BINS + j], (unsigned long long)q);
    }
  }

  // ---------- global ticket: 384th block finalizes ----------
  __threadfence();
  __syncthreads();
  if (tid == 0) tick_sh = atomicAdd(&g_count, 1);
  __syncthreads();
  if (tick_sh != NBLK - 1) return;
  __threadfence();
  if (tid == 0) g_count = 0;                       // reset for next replay

  for (int im = warp; im < NIMG; im += 8) {
    unsigned long long q0 = g_histq[im * BINS + lane];
    unsigned long long q1 = g_histq[im * BINS + 32 + lane];
    g_histq[im * BINS + lane] = 0ULL;              // re-zero for next replay
    g_histq[im * BINS + 32 + lane] = 0ULL;
    float p0 = (float)(long long)q0;
    float p1 = (float)(long long)q1;
#pragma unroll
    for (int d = 1; d < 32; d <<= 1) {
      float t0 = __shfl_up_sync(0xffffffffu, p0, d);
      float t1 = __shfl_up_sync(0xffffffffu, p1, d);
      if (lane >= d) { p0 += t0; p1 += t1; }
    }
    float half0 = __shfl_sync(0xffffffffu, p0, 31);
    float inv   = __frcp_rn(half0 + __shfl_sync(0xffffffffu, p1, 31) + 1e-8f * QS);
    cdf_sh[im][lane]      = p0 * inv;
    cdf_sh[im][lane + 32] = (half0 + p1) * inv;
  }
  __syncthreads();

  float s = 0.0f;
  for (int i = tid; i < NCH * BINS; i += THR) {
    int ch = i >> 6, jj = i & 63;
    s += fabsf(cdf_sh[ch][jj] - cdf_sh[ch + NCH][jj]);
  }
#pragma unroll
  for (int d = 16; d; d >>= 1) s += __shfl_down_sync(0xffffffffu, s, d);
  if (lane == 0) red_sh[warp] = s;
  __syncthreads();
  if (tid == 0) {
    float tot = 0.0f;
#pragma unroll
    for (int wv = 0; wv < 8; ++wv) tot += red_sh[wv];
    out[0] = tot / (float)(NCH * BINS);
  }
}

}  // namespace chl

extern "C" void kernel_launch(void* const* d_in, const int* in_sizes, int n_in,
                              void* d_out, int out_size) {
  const float* pred = (const float*)d_in[0];
  const float* tgt  = (const float*)d_in[1];
  float* out = (float*)d_out;

  chl::k_all<<<chl::NBLK, chl::THR>>>(pred, tgt, out);
}